// round 1
// baseline (speedup 1.0000x reference)
#include <cuda_runtime.h>

// out[i,p] = sum_{m,n} A[i,m] * B[i,n] * C[m,n,p]
// M1 = M2 = MP = 5 (2l+1 for l=2). C is 125 floats, uniform across edges.
//
// Strategy: 4 edges per thread so A/B/out are read/written as float4
// (80 bytes per thread, 16B-aligned). C staged through shared memory,
// consumed in 25-register slices (per-m) to keep register pressure ~100.

#define M1 5
#define M2 5
#define MP 5
#define EPT 4          // edges per thread
#define TPB 256        // threads per block

__global__ __launch_bounds__(TPB)
void cg_combine_kernel(const float* __restrict__ A,
                       const float* __restrict__ B,
                       const float* __restrict__ C,
                       float* __restrict__ out,
                       long long n_edges)
{
    __shared__ float cs[M1 * M2 * MP];  // 125 floats

    int t = threadIdx.x;
    if (t < M1 * M2 * MP) cs[t] = C[t];
    __syncthreads();

    long long tid  = (long long)blockIdx.x * TPB + t;
    long long e0   = tid * EPT;                 // first edge for this thread

    if (e0 + EPT <= n_edges) {
        // ---- fast path: fully vectorized ----
        size_t baseA = (size_t)e0 * M1;         // == e0*5 floats, 80B/thread
        size_t baseB = (size_t)e0 * M2;
        size_t baseO = (size_t)e0 * MP;

        float a[EPT * M1];
        float b[EPT * M2];

        {
            const float4* A4 = reinterpret_cast<const float4*>(A + baseA);
            const float4* B4 = reinterpret_cast<const float4*>(B + baseB);
            float4 av[5], bv[5];
#pragma unroll
            for (int i = 0; i < 5; i++) { av[i] = A4[i]; bv[i] = B4[i]; }
#pragma unroll
            for (int i = 0; i < 5; i++) {
                a[i * 4 + 0] = av[i].x; a[i * 4 + 1] = av[i].y;
                a[i * 4 + 2] = av[i].z; a[i * 4 + 3] = av[i].w;
                b[i * 4 + 0] = bv[i].x; b[i * 4 + 1] = bv[i].y;
                b[i * 4 + 2] = bv[i].z; b[i * 4 + 3] = bv[i].w;
            }
        }

        float acc[EPT * MP];
#pragma unroll
        for (int i = 0; i < EPT * MP; i++) acc[i] = 0.0f;

#pragma unroll
        for (int m = 0; m < M1; m++) {
            // C slice for this m: c[n][p], 25 values
            float c[M2 * MP];
#pragma unroll
            for (int j = 0; j < M2 * MP; j++) c[j] = cs[m * (M2 * MP) + j];

#pragma unroll
            for (int e = 0; e < EPT; e++) {
#pragma unroll
                for (int p = 0; p < MP; p++) {
                    float d = c[0 * MP + p] * b[e * M2 + 0];
#pragma unroll
                    for (int n = 1; n < M2; n++)
                        d = fmaf(b[e * M2 + n], c[n * MP + p], d);
                    acc[e * MP + p] = fmaf(a[e * M1 + m], d, acc[e * MP + p]);
                }
            }
        }

        {
            float4* O4 = reinterpret_cast<float4*>(out + baseO);
            float4 ov[5];
#pragma unroll
            for (int i = 0; i < 5; i++) {
                ov[i].x = acc[i * 4 + 0]; ov[i].y = acc[i * 4 + 1];
                ov[i].z = acc[i * 4 + 2]; ov[i].w = acc[i * 4 + 3];
            }
#pragma unroll
            for (int i = 0; i < 5; i++) O4[i] = ov[i];
        }
    } else if (e0 < n_edges) {
        // ---- tail path (scalar, rarely taken) ----
        for (long long e = e0; e < n_edges; e++) {
            float a[M1], b[M2];
#pragma unroll
            for (int m = 0; m < M1; m++) a[m] = A[e * M1 + m];
#pragma unroll
            for (int n = 0; n < M2; n++) b[n] = B[e * M2 + n];
#pragma unroll
            for (int p = 0; p < MP; p++) {
                float s = 0.0f;
#pragma unroll
                for (int m = 0; m < M1; m++)
#pragma unroll
                    for (int n = 0; n < M2; n++)
                        s = fmaf(a[m] * b[n], cs[(m * M2 + n) * MP + p], s);
                out[e * MP + p] = s;
            }
        }
    }
}

extern "C" void kernel_launch(void* const* d_in, const int* in_sizes, int n_in,
                              void* d_out, int out_size)
{
    const float* A = (const float*)d_in[0];
    const float* B = (const float*)d_in[1];
    const float* C = (const float*)d_in[2];
    float* out = (float*)d_out;

    long long n_edges = (long long)in_sizes[0] / M1;

    long long n_threads = (n_edges + EPT - 1) / EPT;
    int blocks = (int)((n_threads + TPB - 1) / TPB);

    cg_combine_kernel<<<blocks, TPB>>>(A, B, C, out, n_edges);
}

// round 2
// speedup vs baseline: 1.3278x; 1.3278x over previous
#include <cuda_runtime.h>

// out[i,p] = sum_{m,n} A[i,m] * B[i,n] * C[m,n,p]
// M1 = M2 = MP = 5. C is 125 floats, uniform across edges (staged in shared,
// slice stride padded to 32 floats so each per-m slice is 128B-aligned).
//
// Round-2 change vs round-1: EPT 4 -> 2 (float2 loads, 8B-aligned) and
// __launch_bounds__(256,3) to cap registers ~84 -> 3 CTAs/SM = 24 warps.
// Round-1 failed on occupancy: 156 regs -> 1 CTA/SM -> latency-bound.

#define M1 5
#define M2 5
#define MP 5
#define EPT 2          // edges per thread
#define TPB 256        // threads per block
#define CSTRIDE 32     // padded slice stride (floats) -> 128B-aligned slices

__global__ __launch_bounds__(TPB, 3)
void cg_combine_kernel(const float* __restrict__ A,
                       const float* __restrict__ B,
                       const float* __restrict__ C,
                       float* __restrict__ out,
                       long long n_edges)
{
    __shared__ float cs[M1 * CSTRIDE];  // 5 slices of 25 floats, padded

    int t = threadIdx.x;
    if (t < M1 * M2 * MP) {
        int m = t / (M2 * MP);
        int j = t % (M2 * MP);
        cs[m * CSTRIDE + j] = C[t];
    }
    __syncthreads();

    long long tid = (long long)blockIdx.x * TPB + t;
    long long e0  = tid * EPT;                 // first edge for this thread

    if (e0 + EPT <= n_edges) {
        // ---- fast path: float2-vectorized (40B per array per thread) ----
        size_t baseA = (size_t)e0 * M1;
        size_t baseB = (size_t)e0 * M2;
        size_t baseO = (size_t)e0 * MP;

        float a[EPT * M1];
        float b[EPT * M2];

        {
            const float2* A2 = reinterpret_cast<const float2*>(A + baseA);
            const float2* B2 = reinterpret_cast<const float2*>(B + baseB);
            float2 av[5], bv[5];
#pragma unroll
            for (int i = 0; i < 5; i++) { av[i] = A2[i]; bv[i] = B2[i]; }
#pragma unroll
            for (int i = 0; i < 5; i++) {
                a[i * 2 + 0] = av[i].x; a[i * 2 + 1] = av[i].y;
                b[i * 2 + 0] = bv[i].x; b[i * 2 + 1] = bv[i].y;
            }
        }

        float acc[EPT * MP];
#pragma unroll
        for (int i = 0; i < EPT * MP; i++) acc[i] = 0.0f;

#pragma unroll
        for (int m = 0; m < M1; m++) {
            // C slice for this m: c[n][p], 25 values, 128B-aligned in shared
            float c[M2 * MP];
#pragma unroll
            for (int j = 0; j < M2 * MP; j++) c[j] = cs[m * CSTRIDE + j];

#pragma unroll
            for (int e = 0; e < EPT; e++) {
#pragma unroll
                for (int p = 0; p < MP; p++) {
                    float d = c[0 * MP + p] * b[e * M2 + 0];
#pragma unroll
                    for (int n = 1; n < M2; n++)
                        d = fmaf(b[e * M2 + n], c[n * MP + p], d);
                    acc[e * MP + p] = fmaf(a[e * M1 + m], d, acc[e * MP + p]);
                }
            }
        }

        {
            float2* O2 = reinterpret_cast<float2*>(out + baseO);
            float2 ov[5];
#pragma unroll
            for (int i = 0; i < 5; i++) {
                ov[i].x = acc[i * 2 + 0];
                ov[i].y = acc[i * 2 + 1];
            }
#pragma unroll
            for (int i = 0; i < 5; i++) O2[i] = ov[i];
        }
    } else if (e0 < n_edges) {
        // ---- tail path (scalar; not taken for N = 16,777,216) ----
        for (long long e = e0; e < n_edges; e++) {
            float a[M1], b[M2];
#pragma unroll
            for (int m = 0; m < M1; m++) a[m] = A[e * M1 + m];
#pragma unroll
            for (int n = 0; n < M2; n++) b[n] = B[e * M2 + n];
#pragma unroll
            for (int p = 0; p < MP; p++) {
                float s = 0.0f;
#pragma unroll
                for (int m = 0; m < M1; m++)
#pragma unroll
                    for (int n = 0; n < M2; n++)
                        s = fmaf(a[m] * b[n], cs[m * CSTRIDE + n * MP + p], s);
                out[e * MP + p] = s;
            }
        }
    }
}

extern "C" void kernel_launch(void* const* d_in, const int* in_sizes, int n_in,
                              void* d_out, int out_size)
{
    const float* A = (const float*)d_in[0];
    const float* B = (const float*)d_in[1];
    const float* C = (const float*)d_in[2];
    float* out = (float*)d_out;

    long long n_edges = (long long)in_sizes[0] / M1;

    long long n_threads = (n_edges + EPT - 1) / EPT;
    int blocks = (int)((n_threads + TPB - 1) / TPB);

    cg_combine_kernel<<<blocks, TPB>>>(A, B, C, out, n_edges);
}

// round 3
// speedup vs baseline: 1.4213x; 1.0705x over previous
#include <cuda_runtime.h>

// out[i,p] = sum_{m,n} A[i,m] * B[i,n] * C[m,n,p]
// M1 = M2 = MP = 5. C uniform across edges.
//
// Round-3 change: C stored TRANSPOSED in shared as csT[m][p][n] (n contiguous,
// row padded to 8 floats = 32B). Inner loop loads one 5-float column per (m,p)
// just-in-time (LDS.128 + LDS.32, warp-broadcast) instead of holding a 25-reg
// slice. Persistent regs ~55 -> __launch_bounds__(256,4) -> 4 CTAs/SM,
// 32 warps. Round-2 was occupancy-bound at 80 regs / 24 warps (DRAM 63%).

#define M1 5
#define M2 5
#define MP 5
#define EPT 2          // edges per thread
#define TPB 256        // threads per block
#define NPAD 8         // padded n-stride (floats) -> 32B-aligned columns

__global__ __launch_bounds__(TPB, 4)
void cg_combine_kernel(const float* __restrict__ A,
                       const float* __restrict__ B,
                       const float* __restrict__ C,
                       float* __restrict__ out,
                       long long n_edges)
{
    // csT[m][p][n] = C[m][n][p]
    __shared__ float csT[M1][MP][NPAD];

    int t = threadIdx.x;
    if (t < M1 * M2 * MP) {
        int m   = t / (M2 * MP);
        int rem = t % (M2 * MP);
        int n   = rem / MP;
        int p   = rem % MP;
        csT[m][p][n] = C[t];          // t = (m*M2 + n)*MP + p
    }
    __syncthreads();

    long long tid = (long long)blockIdx.x * TPB + t;
    long long e0  = tid * EPT;        // first edge for this thread

    if (e0 + EPT <= n_edges) {
        // ---- fast path: float2-vectorized, streaming loads ----
        size_t baseA = (size_t)e0 * M1;
        size_t baseB = (size_t)e0 * M2;
        size_t baseO = (size_t)e0 * MP;

        // a[k], b[k]: k = edge*5 + component
        float a[EPT * M1];
        float b[EPT * M2];

        {
            const float2* A2 = reinterpret_cast<const float2*>(A + baseA);
            const float2* B2 = reinterpret_cast<const float2*>(B + baseB);
            float2 av[5], bv[5];
#pragma unroll
            for (int i = 0; i < 5; i++) { av[i] = __ldcs(A2 + i); bv[i] = __ldcs(B2 + i); }
#pragma unroll
            for (int i = 0; i < 5; i++) {
                a[i * 2 + 0] = av[i].x; a[i * 2 + 1] = av[i].y;
                b[i * 2 + 0] = bv[i].x; b[i * 2 + 1] = bv[i].y;
            }
        }

        // acc[edge*5 + p]
        float acc[EPT * MP];
#pragma unroll
        for (int i = 0; i < EPT * MP; i++) acc[i] = 0.0f;

#pragma unroll
        for (int m = 0; m < M1; m++) {
            float am0 = a[m];
            float am1 = a[M1 + m];
#pragma unroll
            for (int p = 0; p < MP; p++) {
                // load C column c[n] = C[m][n][p], contiguous 5 floats
                float4 c03 = *reinterpret_cast<const float4*>(&csT[m][p][0]);
                float  c4  = csT[m][p][4];

                float d0 = c03.x * b[0];
                float d1 = c03.x * b[M2 + 0];
                d0 = fmaf(b[1],      c03.y, d0);
                d1 = fmaf(b[M2 + 1], c03.y, d1);
                d0 = fmaf(b[2],      c03.z, d0);
                d1 = fmaf(b[M2 + 2], c03.z, d1);
                d0 = fmaf(b[3],      c03.w, d0);
                d1 = fmaf(b[M2 + 3], c03.w, d1);
                d0 = fmaf(b[4],      c4,    d0);
                d1 = fmaf(b[M2 + 4], c4,    d1);

                acc[p]      = fmaf(am0, d0, acc[p]);
                acc[MP + p] = fmaf(am1, d1, acc[MP + p]);
            }
        }

        {
            float2* O2 = reinterpret_cast<float2*>(out + baseO);
            float2 ov[5];
#pragma unroll
            for (int i = 0; i < 5; i++) {
                ov[i].x = acc[i * 2 + 0];
                ov[i].y = acc[i * 2 + 1];
            }
#pragma unroll
            for (int i = 0; i < 5; i++) __stcs(O2 + i, ov[i]);
        }
    } else if (e0 < n_edges) {
        // ---- tail path (scalar; not taken for N = 16,777,216) ----
        for (long long e = e0; e < n_edges; e++) {
            float a[M1], b[M2];
#pragma unroll
            for (int m = 0; m < M1; m++) a[m] = A[e * M1 + m];
#pragma unroll
            for (int n = 0; n < M2; n++) b[n] = B[e * M2 + n];
#pragma unroll
            for (int p = 0; p < MP; p++) {
                float s = 0.0f;
#pragma unroll
                for (int m = 0; m < M1; m++)
#pragma unroll
                    for (int n = 0; n < M2; n++)
                        s = fmaf(a[m] * b[n], csT[m][p][n], s);
                out[e * MP + p] = s;
            }
        }
    }
}

extern "C" void kernel_launch(void* const* d_in, const int* in_sizes, int n_in,
                              void* d_out, int out_size)
{
    const float* A = (const float*)d_in[0];
    const float* B = (const float*)d_in[1];
    const float* C = (const float*)d_in[2];
    float* out = (float*)d_out;

    long long n_edges = (long long)in_sizes[0] / M1;

    long long n_threads = (n_edges + EPT - 1) / EPT;
    int blocks = (int)((n_threads + TPB - 1) / TPB);

    cg_combine_kernel<<<blocks, TPB>>>(A, B, C, out, n_edges);
}